// round 3
// baseline (speedup 1.0000x reference)
#include <cuda_runtime.h>

// DWT (2x2 Haar) on x: (8, 512, 512, 16) f32 -> 4 bands each (8, 256, 256, 16)
// concatenated in d_out as [LL | LH | HL | HH].
//
// Pure HBM-bound: 128 MiB in + 128 MiB out. Strategy: one thread per
// (b, i, j, c4) where c4 indexes a float4 chunk of the 16-channel dim.
// Each thread loads 4 float4s (the 2x2 pixel quad) and stores 4 float4s
// (one per band). All accesses are 16B-aligned and sector-perfect.

#define B_DIM 8
#define H_DIM 512
#define W_DIM 512
#define C_DIM 16

// In float4 units:
#define ROW_F4   (W_DIM * C_DIM / 4)        // 2048 float4 per input row
#define PIX_F4   (C_DIM / 4)                // 4 float4 per pixel
#define BAND_F4  (B_DIM * (H_DIM/2) * (W_DIM/2) * C_DIM / 4)  // 2,097,152
#define TOTAL_THREADS (B_DIM * (H_DIM/2) * (W_DIM/2) * PIX_F4) // 8,388,608

__global__ __launch_bounds__(256) void dwt_haar_kernel(
    const float4* __restrict__ x, float4* __restrict__ out)
{
    int idx = blockIdx.x * blockDim.x + threadIdx.x;
    // idx layout: [b:3][i:8][j:8][c4:2]
    int c4 = idx & 3;
    int j  = (idx >> 2) & 255;
    int i  = (idx >> 10) & 255;
    int b  = idx >> 18;

    // input base (float4 units): pixel (2i, 2j) of batch b, chunk c4
    int base = ((b * H_DIM + 2 * i) * W_DIM + 2 * j) * PIX_F4 + c4;

    float4 va = x[base];                    // (2i,   2j)
    float4 vb = x[base + PIX_F4];           // (2i,   2j+1)
    float4 vc = x[base + ROW_F4];           // (2i+1, 2j)
    float4 vd = x[base + ROW_F4 + PIX_F4];  // (2i+1, 2j+1)

    // Butterfly: s0=a+d, s1=b+c, d0=a-d, d1=b-c
    // LL=(s0+s1)/2, LH=(d0-d1)/2, HL=(d0+d1)/2, HH=(s0-s1)/2
    float4 ll, lh, hl, hh;
    {
        float s0, s1, d0, d1;
        s0 = va.x + vd.x; s1 = vb.x + vc.x; d0 = va.x - vd.x; d1 = vb.x - vc.x;
        ll.x = (s0 + s1) * 0.5f; lh.x = (d0 - d1) * 0.5f;
        hl.x = (d0 + d1) * 0.5f; hh.x = (s0 - s1) * 0.5f;
        s0 = va.y + vd.y; s1 = vb.y + vc.y; d0 = va.y - vd.y; d1 = vb.y - vc.y;
        ll.y = (s0 + s1) * 0.5f; lh.y = (d0 - d1) * 0.5f;
        hl.y = (d0 + d1) * 0.5f; hh.y = (s0 - s1) * 0.5f;
        s0 = va.z + vd.z; s1 = vb.z + vc.z; d0 = va.z - vd.z; d1 = vb.z - vc.z;
        ll.z = (s0 + s1) * 0.5f; lh.z = (d0 - d1) * 0.5f;
        hl.z = (d0 + d1) * 0.5f; hh.z = (s0 - s1) * 0.5f;
        s0 = va.w + vd.w; s1 = vb.w + vc.w; d0 = va.w - vd.w; d1 = vb.w - vc.w;
        ll.w = (s0 + s1) * 0.5f; lh.w = (d0 - d1) * 0.5f;
        hl.w = (d0 + d1) * 0.5f; hh.w = (s0 - s1) * 0.5f;
    }

    // output base (float4 units) inside one band
    int obase = ((b * (H_DIM/2) + i) * (W_DIM/2) + j) * PIX_F4 + c4;

    out[obase]               = ll;
    out[obase + BAND_F4]     = lh;
    out[obase + 2 * BAND_F4] = hl;
    out[obase + 3 * BAND_F4] = hh;
}

extern "C" void kernel_launch(void* const* d_in, const int* in_sizes, int n_in,
                              void* d_out, int out_size)
{
    (void)in_sizes; (void)n_in; (void)out_size;
    const float4* x = (const float4*)d_in[0];
    float4* out = (float4*)d_out;
    dim3 block(256);
    dim3 grid(TOTAL_THREADS / 256);
    dwt_haar_kernel<<<grid, block>>>(x, out);
}

// round 5
// speedup vs baseline: 1.0043x; 1.0043x over previous
#include <cuda_runtime.h>

// DWT (2x2 Haar): x (8,512,512,16) f32 -> 4 bands (8,256,256,16), concat [LL|LH|HL|HH].
//
// Warp-coalesced version: lanes map linearly onto the input row-pair so each
// warp-wide LDG.128 covers a dense 512B span (4 full 128B lines). The a<->b
// pixel exchange is done with shfl_xor(4). Even-parity lanes produce LL & LH,
// odd-parity lanes produce HL & HH (sign trick), so each STG.128 covers two
// dense 256B spans. Streaming hints (__ldcs/__stcs): every line touched once.
//
// Per warp: 4 output pixels (8 input pixels across 2 rows).
//   lane = linear float4 index in the 8-pixel row segment
//   p = lane>>2 (pixel 0..7), parity = p&1 (a vs b), pp = lane>>3 (pair 0..3),
//   c4 = lane&3 (channel chunk)

#define BAND_F4 (8 * 256 * 256 * 16 / 4)   // 2,097,152 float4 per band
#define TOTAL_THREADS (8 * 256 * 64 * 32)  // 4,194,304  (1 warp = 4 out pixels)

__global__ __launch_bounds__(256) void dwt_haar_kernel(
    const float4* __restrict__ x, float4* __restrict__ out)
{
    int t    = blockIdx.x * 256 + threadIdx.x;
    int lane = t & 31;
    int w    = t >> 5;
    // warp decomposition: [b:3][i:8][g:6], g = group of 4 output pixels
    int g = w & 63;
    int i = (w >> 6) & 255;
    int b = w >> 14;

    // input: rows 2i and 2i+1 of batch b, float4 offset g*32 + lane
    // (one input row = 512 px * 4 f4 = 2048 f4)
    int ibase = (b * 512 + 2 * i) * 2048 + g * 32 + lane;
    float4 v0 = __ldcs(x + ibase);          // row 2i
    float4 v1 = __ldcs(x + ibase + 2048);   // row 2i+1

    // exchange with the partner pixel (a<->b, c<->d): lane ^ 4
    float4 t0, t1;
    t0.x = __shfl_xor_sync(0xFFFFFFFFu, v0.x, 4);
    t0.y = __shfl_xor_sync(0xFFFFFFFFu, v0.y, 4);
    t0.z = __shfl_xor_sync(0xFFFFFFFFu, v0.z, 4);
    t0.w = __shfl_xor_sync(0xFFFFFFFFu, v0.w, 4);
    t1.x = __shfl_xor_sync(0xFFFFFFFFu, v1.x, 4);
    t1.y = __shfl_xor_sync(0xFFFFFFFFu, v1.y, 4);
    t1.z = __shfl_xor_sync(0xFFFFFFFFu, v1.z, 4);
    t1.w = __shfl_xor_sync(0xFFFFFFFFu, v1.w, 4);

    // sum0 = a+b (both parities agree), dif0 = +/-(a-b); same for row1 (c,d)
    float4 sum0, dif0, sum1, dif1;
    sum0.x = v0.x + t0.x; dif0.x = v0.x - t0.x;
    sum0.y = v0.y + t0.y; dif0.y = v0.y - t0.y;
    sum0.z = v0.z + t0.z; dif0.z = v0.z - t0.z;
    sum0.w = v0.w + t0.w; dif0.w = v0.w - t0.w;
    sum1.x = v1.x + t1.x; dif1.x = v1.x - t1.x;
    sum1.y = v1.y + t1.y; dif1.y = v1.y - t1.y;
    sum1.z = v1.z + t1.z; dif1.z = v1.z - t1.z;
    sum1.w = v1.w + t1.w; dif1.w = v1.w - t1.w;

    int  odd = (lane >> 2) & 1;          // pixel parity: 0 = a/c lane, 1 = b/d lane
    float sgn = odd ? -1.0f : 1.0f;

    // even lanes: o1 = LL = (sum0+sum1)/2,  o2 = LH = (dif0+dif1)/2
    // odd  lanes: o1 = HL = (sum0-sum1)/2,  o2 = HH = (dif1-dif0)/2
    float4 o1, o2;
    o1.x = (sum0.x + sgn * sum1.x) * 0.5f;  o2.x = (dif1.x + sgn * dif0.x) * 0.5f;
    o1.y = (sum0.y + sgn * sum1.y) * 0.5f;  o2.y = (dif1.y + sgn * dif0.y) * 0.5f;
    o1.z = (sum0.z + sgn * sum1.z) * 0.5f;  o2.z = (dif1.z + sgn * dif0.z) * 0.5f;
    o1.w = (sum0.w + sgn * sum1.w) * 0.5f;  o2.w = (dif1.w + sgn * dif0.w) * 0.5f;

    // output pixel (i, jout) chunk c4; bands: even -> {LL, LH}, odd -> {HL, HH}
    int pp   = lane >> 3;       // pair index within warp (0..3)
    int c4   = lane & 3;
    int jout = g * 4 + pp;
    int obase = ((b * 256 + i) * 256 + jout) * 4 + c4;
    int off1  = odd ? 2 * BAND_F4 : 0;

    __stcs(out + obase + off1,           o1);   // LL or HL
    __stcs(out + obase + off1 + BAND_F4, o2);   // LH or HH
}

extern "C" void kernel_launch(void* const* d_in, const int* in_sizes, int n_in,
                              void* d_out, int out_size)
{
    (void)in_sizes; (void)n_in; (void)out_size;
    const float4* x = (const float4*)d_in[0];
    float4* out = (float4*)d_out;
    dwt_haar_kernel<<<TOTAL_THREADS / 256, 256>>>(x, out);
}